// round 1
// baseline (speedup 1.0000x reference)
#include <cuda_runtime.h>
#include <cstdint>

#define IN_F    128
#define OUT_F   64
#define NK      8      // NUM + K spline basis count
#define NF      10     // 8 spline fields + silu field + linear field
#define TM      128    // rows per CTA
#define CI      4      // features per chunk
#define THREADS 256

typedef unsigned long long u64;

// Prepped weights: [i][f][o], f in 0..7 = coef*scale_sp*mask (k-slices),
// f=8 = scale_base*mask, f=9 = W1^T.  320 KB static device scratch.
__device__ float g_wt[IN_F * NF * OUT_F];

__global__ void prep_kernel(const float* __restrict__ W1,
                            const float* __restrict__ coef,
                            const float* __restrict__ scale_base,
                            const float* __restrict__ scale_sp,
                            const float* __restrict__ mask) {
    int idx = blockIdx.x * blockDim.x + threadIdx.x;
    if (idx >= IN_F * NF * OUT_F) return;
    int o = idx % OUT_F;
    int f = (idx / OUT_F) % NF;
    int i = idx / (OUT_F * NF);
    float v;
    if (f < NK) {
        v = coef[(i * OUT_F + o) * NK + f] * scale_sp[i * OUT_F + o] * mask[i * OUT_F + o];
    } else if (f == NK) {
        v = scale_base[i * OUT_F + o] * mask[i * OUT_F + o];
    } else {
        v = W1[o * IN_F + i];
    }
    g_wt[idx] = v;
}

__device__ __forceinline__ u64 pk2(float v) {
    unsigned r = __float_as_uint(v);
    u64 d;
    asm("mov.b64 %0, {%1, %2};" : "=l"(d) : "r"(r), "r"(r));
    return d;
}
__device__ __forceinline__ void upk2(u64 v, float& lo, float& hi) {
    unsigned a, b;
    asm("mov.b64 {%0, %1}, %2;" : "=r"(a), "=r"(b) : "l"(v));
    lo = __uint_as_float(a);
    hi = __uint_as_float(b);
}
__device__ __forceinline__ u64 fma2(u64 a, u64 b, u64 c) {
    u64 d;
    asm("fma.rn.f32x2 %0, %1, %2, %3;" : "=l"(d) : "l"(a), "l"(b), "l"(c));
    return d;
}

__global__ __launch_bounds__(THREADS, 2)
void enc_main_kernel(const float* __restrict__ x,
                     const float* __restrict__ grid,
                     float* __restrict__ zout,
                     float* __restrict__ xlout,
                     int N) {
    __shared__ __align__(16) float sS[CI][NF][TM];        // per-(row,feature) scalars
    __shared__ __align__(16) float sW[CI * NF * OUT_F];   // weight fields for chunk

    const int t    = threadIdx.x;
    const int cg   = t & 15;        // col group: cols cg*4 .. cg*4+3
    const int rg   = t >> 4;        // row group: rows rg*8 .. rg*8+7
    const int row0 = rg * 8;
    const int n0   = blockIdx.x * TM;

    const float g0   = grid[0];                 // first extended knot (~ -2.2)
    const float invh = 1.0f / (grid[1] - grid[0]);

    // f32x2 accumulators: lanes = (row 2a, row 2a+1), index b = col
    u64 accz[4][4], accx[4][4];
#pragma unroll
    for (int a = 0; a < 4; a++)
#pragma unroll
        for (int b = 0; b < 4; b++) { accz[a][b] = 0ULL; accx[a][b] = 0ULL; }

    // scalar-prep assignment: each thread handles 1 row x 2 features
    const int prow  = t >> 1;         // 0..127
    const int ibase = (t & 1) * 2;    // 0 or 2
    const int gn    = (n0 + prow < N) ? (n0 + prow) : (N - 1);
    const float* xrow = x + (size_t)gn * IN_F;

    for (int i0 = 0; i0 < IN_F; i0 += CI) {
        // ---- stage weight fields for this feature chunk ----
        {
            const float4* src = (const float4*)(g_wt + i0 * (NF * OUT_F));
            float4* dst = (float4*)sW;
            for (int p = t; p < (CI * NF * OUT_F) / 4; p += THREADS)
                dst[p] = src[p];
        }

        // ---- per-(row, feature) scalar prep ----
        float2 xv = *(const float2*)(xrow + i0 + ibase);
#pragma unroll
        for (int e = 0; e < 2; e++) {
            float a = e ? xv.y : xv.x;
            float s = a / (1.0f + __expf(-a));         // silu
            float tt = (a - g0) * invh;
            float mf = floorf(tt);
            float u  = tt - mf;
            float w0 = 0.f, w1 = 0.f, w2 = 0.f, w3 = 0.f;
            int   m  = 100;                             // invalid -> all zero
            if (tt >= 0.0f && mf <= 10.0f) {
                m = (int)mf;
                float u2 = u * u, u3 = u2 * u;
                float omu = 1.0f - u;
                w0 = (1.0f / 6.0f) * omu * omu * omu;
                w1 = (1.0f / 6.0f) * (3.0f * u3 - 6.0f * u2 + 4.0f);
                w2 = (1.0f / 6.0f) * (-3.0f * u3 + 3.0f * u2 + 3.0f * u + 1.0f);
                w3 = (1.0f / 6.0f) * u3;
            }
            int ii = ibase + e;
#pragma unroll
            for (int j = 0; j < 8; j++) {
                int r = j - m + 3;                      // which of the 4 weights lands on slot j
                float w = (r == 0) ? w0 : (r == 1) ? w1 : (r == 2) ? w2 : (r == 3) ? w3 : 0.0f;
                sS[ii][j][prow] = w;
            }
            sS[ii][8][prow] = s;
            sS[ii][9][prow] = a;
        }
        __syncthreads();

        // ---- register-tiled outer-product accumulation ----
#pragma unroll
        for (int ii = 0; ii < CI; ii++) {
#pragma unroll
            for (int f = 0; f < NF; f++) {
                const float4 wv = *(const float4*)(sW + (ii * NF + f) * OUT_F + cg * 4);
                u64 ww[4];
                ww[0] = pk2(wv.x); ww[1] = pk2(wv.y); ww[2] = pk2(wv.z); ww[3] = pk2(wv.w);
                const u64* sr = (const u64*)&sS[ii][f][row0];
                u64 rr[4];
                rr[0] = sr[0]; rr[1] = sr[1]; rr[2] = sr[2]; rr[3] = sr[3];
                if (f < 9) {
#pragma unroll
                    for (int a = 0; a < 4; a++)
#pragma unroll
                        for (int b = 0; b < 4; b++)
                            accz[a][b] = fma2(rr[a], ww[b], accz[a][b]);
                } else {
#pragma unroll
                    for (int a = 0; a < 4; a++)
#pragma unroll
                        for (int b = 0; b < 4; b++)
                            accx[a][b] = fma2(rr[a], ww[b], accx[a][b]);
                }
            }
        }
        __syncthreads();
    }

    // ---- epilogue: row-norm reduce across the 16 col-groups, scale, store ----
    float zf[8][4], xf[8][4];
#pragma unroll
    for (int a = 0; a < 4; a++)
#pragma unroll
        for (int b = 0; b < 4; b++) {
            upk2(accz[a][b], zf[2 * a][b], zf[2 * a + 1][b]);
            upk2(accx[a][b], xf[2 * a][b], xf[2 * a + 1][b]);
        }

    float ssq[8];
#pragma unroll
    for (int r = 0; r < 8; r++)
        ssq[r] = zf[r][0] * zf[r][0] + zf[r][1] * zf[r][1]
               + zf[r][2] * zf[r][2] + zf[r][3] * zf[r][3];

#pragma unroll
    for (int msk = 1; msk < 16; msk <<= 1)
#pragma unroll
        for (int r = 0; r < 8; r++)
            ssq[r] += __shfl_xor_sync(0xffffffffu, ssq[r], msk);

#pragma unroll
    for (int r = 0; r < 8; r++) {
        int n = n0 + row0 + r;
        if (n < N) {
            float norm = sqrtf(ssq[r]);
            float fac  = 0.8f / fmaxf(norm, 1e-12f);
            float4 zv = make_float4(zf[r][0] * fac, zf[r][1] * fac,
                                    zf[r][2] * fac, zf[r][3] * fac);
            float4 xv = make_float4(xf[r][0], xf[r][1], xf[r][2], xf[r][3]);
            *(float4*)(zout + (size_t)n * OUT_F + cg * 4) = zv;
            *(float4*)(xlout + (size_t)n * OUT_F + cg * 4) = xv;
        }
    }
}

extern "C" void kernel_launch(void* const* d_in, const int* in_sizes, int n_in,
                              void* d_out, int out_size) {
    const float* x          = (const float*)d_in[0];
    const float* W1         = (const float*)d_in[1];
    const float* grid       = (const float*)d_in[2];
    const float* coef       = (const float*)d_in[3];
    const float* scale_base = (const float*)d_in[4];
    const float* scale_sp   = (const float*)d_in[5];
    const float* mask       = (const float*)d_in[6];
    // d_in[7] = edge_index: unused by the reference computation

    const int N = in_sizes[0] / IN_F;
    float* out   = (float*)d_out;
    float* zout  = out;                       // z first
    float* xlout = out + (size_t)N * OUT_F;   // then x_lin

    prep_kernel<<<(IN_F * NF * OUT_F + 255) / 256, 256>>>(W1, coef, scale_base, scale_sp, mask);
    enc_main_kernel<<<(N + TM - 1) / TM, THREADS>>>(x, grid, zout, xlout, N);
}